// round 1
// baseline (speedup 1.0000x reference)
#include <cuda_runtime.h>

#define N_NODES 50000
#define F1 64      // latent (layer-1 input width)
#define F2 128     // hidden
#define F3 64      // output width
#define MAX_E 800000

// ---------------- device scratch (no allocations allowed) ----------------
__device__ float g_deg  [N_NODES];
__device__ float g_dinv [N_NODES];
__device__ float g_dinv2[N_NODES];
__device__ float g_norm [MAX_E];
__device__ float g_agg1 [N_NODES * F1];          // Â z
__device__ float g_x    [N_NODES * F2];          // relu(Âz @ W1 + b1)
__device__ float g_h2   [N_NODES * F3];          // x @ W2
__device__ float g_agg2 [N_NODES * F3];          // Â h2 (edge part)
__device__ int   g_is64;

// ---------------- helpers ----------------
__device__ __forceinline__ int eidx(const void* ei, int is64, long long p) {
    return is64 ? (int)((const long long*)ei)[p] : ((const int*)ei)[p];
}

__device__ __forceinline__ void red4(float* p, float x, float y, float z, float w) {
    asm volatile("red.global.add.v4.f32 [%0], {%1,%2,%3,%4};"
                 :: "l"(p), "f"(x), "f"(y), "f"(z), "f"(w) : "memory");
}

// ---------------- dtype detection ----------------
__global__ void detect_kernel(const long long* ei) {
    if (threadIdx.x == 0) {
        bool ok = true;
#pragma unroll
        for (int i = 0; i < 8; i++) {
            long long v = ei[i];
            if (v < 0 || v >= N_NODES) ok = false;
        }
        g_is64 = ok ? 1 : 0;   // int32 data read as int64 is out of range
    }
}

// ---------------- init: deg = 1 (self loop), zero agg buffers ----------------
__global__ void init_kernel(int M) {
    int i = blockIdx.x * 256 + threadIdx.x;
    if (i < M) g_deg[i] = 1.0f;
    if (i < M * (F1 / 4)) {
        float4 zv = make_float4(0.f, 0.f, 0.f, 0.f);
        ((float4*)g_agg1)[i] = zv;
        ((float4*)g_agg2)[i] = zv;
    }
}

// ---------------- degree accumulation over explicit edges ----------------
__global__ void deg_kernel(const void* ei, int nE) {
    int e = blockIdx.x * 256 + threadIdx.x;
    if (e >= nE) return;
    int d = eidx(ei, g_is64, (long long)nE + e);
    atomicAdd(&g_deg[d], 1.0f);
}

__global__ void dinv_kernel(int M) {
    int i = blockIdx.x * 256 + threadIdx.x;
    if (i >= M) return;
    float r = rsqrtf(g_deg[i]);
    g_dinv[i]  = r;
    g_dinv2[i] = r * r;
}

__global__ void norm_kernel(const void* ei, int nE) {
    int e = blockIdx.x * 256 + threadIdx.x;
    if (e >= nE) return;
    int is64 = g_is64;
    int s = eidx(ei, is64, e);
    int d = eidx(ei, is64, (long long)nE + e);
    g_norm[e] = g_dinv[s] * g_dinv[d];
}

// ---------------- 64-wide edge aggregation: agg[dst] += feat[src]*norm ----------------
__device__ __forceinline__ void agg_body(const float4* __restrict__ feat,
                                         float* __restrict__ agg,
                                         const void* ei, int nE) {
    long long t = (long long)blockIdx.x * 256 + threadIdx.x;
    long long e = t >> 4;
    if (e >= nE) return;
    int j = (int)(t & 15);
    int is64 = g_is64;
    int s = eidx(ei, is64, e);
    int d = eidx(ei, is64, (long long)nE + e);
    float nm = g_norm[e];
    float4 v = feat[s * 16 + j];
    red4(agg + ((long long)d * 16 + j) * 4, v.x * nm, v.y * nm, v.z * nm, v.w * nm);
}

__global__ __launch_bounds__(256) void agg1_kernel(const float4* __restrict__ z,
                                                   const void* ei, int nE) {
    agg_body(z, g_agg1, ei, nE);
}

__global__ __launch_bounds__(256) void agg2_kernel(const void* ei, int nE) {
    agg_body((const float4*)g_h2, g_agg2, ei, nE);
}

// ---------------- GEMM1: x = relu( (agg1 + z*dinv2) @ W1 + b1 )  [M,64]x[64,128] ----------------
__global__ __launch_bounds__(256) void gemm1_kernel(const float4* __restrict__ z4,
                                                    const float* __restrict__ W1,
                                                    const float* __restrict__ b1,
                                                    int M) {
    __shared__ float  Ws[F1 * F2];        // 64x128 = 32 KB
    __shared__ float4 As4[64 * 16];       // 64 rows x 64 floats = 16 KB
    int tid = threadIdx.x;
    int m0  = blockIdx.x * 64;

    // load W1 (2048 float4)
    const float4* W14 = (const float4*)W1;
    float4* Ws4 = (float4*)Ws;
#pragma unroll
    for (int i = 0; i < 8; i++) Ws4[tid + 256 * i] = W14[tid + 256 * i];

    // load A tile with fused self-loop term
    const float4* ag4 = (const float4*)g_agg1;
#pragma unroll
    for (int i = 0; i < 4; i++) {
        int t   = tid + 256 * i;          // 0..1023
        int row = m0 + (t >> 4);
        float4 a = make_float4(0.f, 0.f, 0.f, 0.f);
        if (row < M) {
            float4 g  = ag4[(long long)row * 16 + (t & 15)];
            float4 zz = z4 [(long long)row * 16 + (t & 15)];
            float  sc = g_dinv2[row];
            a.x = g.x + zz.x * sc;
            a.y = g.y + zz.y * sc;
            a.z = g.z + zz.z * sc;
            a.w = g.w + zz.w * sc;
        }
        As4[t] = a;
    }
    __syncthreads();

    int tx = tid & 31, ty = tid >> 5;
    int c = tx * 4, r0 = ty * 8;
    float acc[8][4];
#pragma unroll
    for (int i = 0; i < 8; i++)
#pragma unroll
        for (int jj = 0; jj < 4; jj++) acc[i][jj] = 0.f;

    const float* As = (const float*)As4;
#pragma unroll
    for (int k = 0; k < F1; k++) {
        float4 w = *(const float4*)&Ws[k * F2 + c];
#pragma unroll
        for (int i = 0; i < 8; i++) {
            float a = As[(r0 + i) * F1 + k];
            acc[i][0] += a * w.x;
            acc[i][1] += a * w.y;
            acc[i][2] += a * w.z;
            acc[i][3] += a * w.w;
        }
    }

    float4 bb = *(const float4*)&b1[c];
#pragma unroll
    for (int i = 0; i < 8; i++) {
        int m = m0 + r0 + i;
        if (m < M) {
            float4 o;
            o.x = fmaxf(acc[i][0] + bb.x, 0.f);
            o.y = fmaxf(acc[i][1] + bb.y, 0.f);
            o.z = fmaxf(acc[i][2] + bb.z, 0.f);
            o.w = fmaxf(acc[i][3] + bb.w, 0.f);
            ((float4*)g_x)[(long long)m * 32 + tx] = o;
        }
    }
}

// ---------------- GEMM2: h2 = x @ W2   [M,128]x[128,64] ----------------
__global__ __launch_bounds__(256) void gemm2_kernel(const float* __restrict__ W2, int M) {
    __shared__ float  Ws[F2 * F3];        // 128x64 = 32 KB
    __shared__ float4 As4[64 * 8];        // 64 rows x 32 floats (one K-chunk) = 8 KB
    int tid = threadIdx.x;
    int m0  = blockIdx.x * 64;

    const float4* W24 = (const float4*)W2;
    float4* Ws4 = (float4*)Ws;
#pragma unroll
    for (int i = 0; i < 8; i++) Ws4[tid + 256 * i] = W24[tid + 256 * i];

    int tx = tid & 15, ty = tid >> 4;
    float acc[4][4];
#pragma unroll
    for (int i = 0; i < 4; i++)
#pragma unroll
        for (int jj = 0; jj < 4; jj++) acc[i][jj] = 0.f;

    const float* As = (const float*)As4;
    const float4* x4 = (const float4*)g_x;

    for (int kc = 0; kc < 4; kc++) {
        __syncthreads();
#pragma unroll
        for (int i = 0; i < 2; i++) {
            int t   = tid + 256 * i;      // 0..511
            int row = m0 + (t >> 3);
            int c4  = t & 7;
            float4 a = make_float4(0.f, 0.f, 0.f, 0.f);
            if (row < M) a = x4[(long long)row * 32 + kc * 8 + c4];
            As4[t] = a;
        }
        __syncthreads();
#pragma unroll
        for (int kk = 0; kk < 32; kk++) {
            int k = kc * 32 + kk;
            float4 w = *(const float4*)&Ws[k * F3 + tx * 4];
#pragma unroll
            for (int i = 0; i < 4; i++) {
                float a = As[(ty * 4 + i) * 32 + kk];
                acc[i][0] += a * w.x;
                acc[i][1] += a * w.y;
                acc[i][2] += a * w.z;
                acc[i][3] += a * w.w;
            }
        }
    }

#pragma unroll
    for (int i = 0; i < 4; i++) {
        int m = m0 + ty * 4 + i;
        if (m < M) {
            float4 o = make_float4(acc[i][0], acc[i][1], acc[i][2], acc[i][3]);
            ((float4*)g_h2)[(long long)m * 16 + tx] = o;
        }
    }
}

// ---------------- epilogue: out = relu(agg2 + h2*dinv2 + b2) ----------------
__global__ __launch_bounds__(256) void epilogue_kernel(const float* __restrict__ b2,
                                                       float* __restrict__ out, int M) {
    int i = blockIdx.x * 256 + threadIdx.x;     // over M*16 float4
    if (i >= M * 16) return;
    int m = i >> 4;
    float s = g_dinv2[m];
    float4 a = ((const float4*)g_agg2)[i];
    float4 h = ((const float4*)g_h2)[i];
    int c = (i & 15) * 4;
    float4 b = *(const float4*)(b2 + c);
    float4 o;
    o.x = fmaxf(a.x + h.x * s + b.x, 0.f);
    o.y = fmaxf(a.y + h.y * s + b.y, 0.f);
    o.z = fmaxf(a.z + h.z * s + b.z, 0.f);
    o.w = fmaxf(a.w + h.w * s + b.w, 0.f);
    ((float4*)out)[i] = o;
}

// ---------------- launch ----------------
extern "C" void kernel_launch(void* const* d_in, const int* in_sizes, int n_in,
                              void* d_out, int out_size) {
    const float* z  = (const float*)d_in[0];
    const void*  ei = d_in[1];
    const float* W1 = (const float*)d_in[2];
    const float* b1 = (const float*)d_in[3];
    const float* W2 = (const float*)d_in[4];
    const float* b2 = (const float*)d_in[5];
    float* out = (float*)d_out;

    int nE = in_sizes[1] / 2;          // 800000
    int M  = in_sizes[0] / F1;         // 50000

    int nb_nodes = (M + 255) / 256;
    int nb_init  = (M * (F1 / 4) + 255) / 256;
    int nb_edge  = (nE + 255) / 256;
    long long aggT = (long long)nE * 16;
    int nb_agg   = (int)((aggT + 255) / 256);
    int nb_gemm  = (M + 63) / 64;
    int nb_epi   = (M * 16 + 255) / 256;

    detect_kernel<<<1, 32>>>((const long long*)ei);
    init_kernel<<<nb_init, 256>>>(M);
    deg_kernel<<<nb_edge, 256>>>(ei, nE);
    dinv_kernel<<<nb_nodes, 256>>>(M);
    norm_kernel<<<nb_edge, 256>>>(ei, nE);
    agg1_kernel<<<nb_agg, 256>>>((const float4*)z, ei, nE);
    gemm1_kernel<<<nb_gemm, 256>>>((const float4*)z, W1, b1, M);
    gemm2_kernel<<<nb_gemm, 256>>>(W2, M);
    agg2_kernel<<<nb_agg, 256>>>(ei, nE);
    epilogue_kernel<<<nb_epi, 256>>>(b2, out, M);
}